// round 12
// baseline (speedup 1.0000x reference)
#include <cuda_runtime.h>
#include <cuda_bf16.h>
#include <cstdint>

typedef uint32_t u32; typedef unsigned short u16; typedef unsigned long long u64;

#define DD 256
#define NCTA 148
#define NTHREADS 512

// ---- smem byte offsets ----
#define A_HI 0                      // rows 0-63 bf16 hi plane (swizzled) 32KB
#define A_LO 32768                  // lo plane 32KB
#define AF32 65536                  // rows 64-127 f32 [row][col] 64KB
#define BH_OFF 131072               // 2 slots x [2 plane][256 n x 48B] = 48KB
#define BROW 48
#define BPLANE (256 * BROW)         // 12288
#define BBUF (2 * BPLANE)           // 24576
#define BF_OFF (BH_OFF + 2 * BBUF)  // 180224: 2 slots x 16KB f32 [k16][256]
#define SMEM_TOTAL (BF_OFF + 2 * 16384)   // 212992 (208 KB)

// ---- device scratch ----
__device__ float d_p[2 * DD];
__device__ __align__(16) __nv_bfloat16 d_Bw[6][2][16][256][16];  // bf16 hi/lo planes
__device__ __align__(16) float d_Bf[6][16][16][256];             // f32 [L][ck][k][n]

// ---- helpers ----
__device__ __forceinline__ u32 smem_u32(const void* p) {
    u32 a;
    asm("{ .reg .u64 t; cvta.to.shared.u64 t, %1; cvt.u32.u64 %0, t; }" : "=r"(a) : "l"(p));
    return a;
}
__device__ __forceinline__ float fast_tanh(float x) {
    float e, r;
    asm("ex2.approx.f32 %0, %1;" : "=f"(e) : "f"(x * 2.8853900817779268f));
    asm("rcp.approx.f32 %0, %1;" : "=f"(r) : "f"(e + 1.0f));
    return 1.0f - 2.0f * r;
}
__device__ __forceinline__ void split2(float a, float b, u32& h, u32& l) {
    u16 ha = __bfloat16_as_ushort(__float2bfloat16_rn(a));
    u16 hb = __bfloat16_as_ushort(__float2bfloat16_rn(b));
    float fa = __bfloat162float(__ushort_as_bfloat16(ha));
    float fb = __bfloat162float(__ushort_as_bfloat16(hb));
    u16 la = __bfloat16_as_ushort(__float2bfloat16_rn(a - fa));
    u16 lb = __bfloat16_as_ushort(__float2bfloat16_rn(b - fb));
    h = ((u32)hb << 16) | ha;
    l = ((u32)lb << 16) | la;
}
__device__ __forceinline__ int aoff(int row, int col) {
    return row * 512 + ((((col >> 3) ^ (row & 7)) << 4) | ((col & 7) << 1));
}
__device__ __forceinline__ void ffma2(u64& d, u64 a, u64 b) {
    asm("fma.rn.f32x2 %0, %1, %2, %0;" : "+l"(d) : "l"(a), "l"(b));
}
__device__ __forceinline__ u64 dup2(float a) {
    u64 r; asm("mov.b64 %0, {%1, %1};" : "=l"(r) : "f"(a)); return r;
}
__device__ __forceinline__ float2 unpack2(u64 v) {
    float2 r; asm("mov.b64 {%0, %1}, %2;" : "=f"(r.x), "=f"(r.y) : "l"(v)); return r;
}

#define LDSM4(r, addr) \
    asm volatile("ldmatrix.sync.aligned.m8n8.x4.shared.b16 {%0,%1,%2,%3}, [%4];" \
        : "=r"((r)[0]), "=r"((r)[1]), "=r"((r)[2]), "=r"((r)[3]) : "r"(addr))
#define MMA(d, a, b0, b1) \
    asm volatile("mma.sync.aligned.m16n8k16.row.col.f32.bf16.bf16.f32 " \
        "{%0,%1,%2,%3}, {%4,%5,%6,%7}, {%8,%9}, {%0,%1,%2,%3};" \
        : "+f"((d)[0]), "+f"((d)[1]), "+f"((d)[2]), "+f"((d)[3]) \
        : "r"((a)[0]), "r"((a)[1]), "r"((a)[2]), "r"((a)[3]), "r"(b0), "r"(b1))
#define CPASYNC16(dst, src) \
    asm volatile("cp.async.cg.shared.global [%0], [%1], 16;" :: "r"(dst), "l"(src))

// ---- fused prologue: weight split/reorder (bf16 planes + f32 image) + p ----
__global__ void prep(const float* __restrict__ w0, const float* __restrict__ w1,
                     const float* __restrict__ u1cw, const float* __restrict__ w2,
                     const float* __restrict__ u2cw, const float* __restrict__ wo,
                     const float* __restrict__ u1w, const float* __restrict__ u2w) {
    int b = blockIdx.x;
    if (b < 1536) {
        int L = b >> 8, n = b & 255, k = threadIdx.x;
        const float* W; bool direct;
        switch (L) {
            case 0: W = w0;   direct = false; break;
            case 1: W = w1;   direct = false; break;
            case 2: W = u1cw; direct = true;  break;
            case 3: W = w2;   direct = false; break;
            case 4: W = u2cw; direct = true;  break;
            default: W = wo;  direct = false; break;
        }
        float wv = direct ? W[k * DD + n] : W[n * DD + k];
        __nv_bfloat16 h = __float2bfloat16_rn(wv);
        __nv_bfloat16 l = __float2bfloat16_rn(wv - __bfloat162float(h));
        d_Bw[L][0][k >> 4][n][k & 15] = h;
        d_Bw[L][1][k >> 4][n][k & 15] = l;
        d_Bf[L][k >> 4][k & 15][n] = wv;
    } else {
        int t = (b - 1536) * 256 + threadIdx.x;
        const float* w = (t < DD) ? u1w : u2w;
        int j = t & (DD - 1);
        float prod = 1.0f / (float)DD;
        #pragma unroll
        for (int d = 0; d < 9; ++d)
            #pragma unroll
            for (int g = 0; g < 3; ++g) {
                float c = cosf(w[(d * DD + j) * DD + g]);
                prod *= c * c;
            }
        d_p[t] = prod;
    }
}

// ---- FFMA microkernel: one k16 chunk for RT rows/thread ----
template<int RT>
__device__ __forceinline__ void ffma_chunk(const unsigned char* sm, u64 acc[8][4],
                                           int slot, int kb, int trow, int jlo, int jhi) {
    const float* Bf  = (const float*)(sm + BF_OFF + slot * 16384);
    const float* A32 = (const float*)(sm + AF32);
    #pragma unroll
    for (int kk = 0; kk < 8; ++kk) {
        const int k = 2 * kk;
        ulonglong2 bl = *(const ulonglong2*)&Bf[k * 256 + jlo];
        ulonglong2 bh = *(const ulonglong2*)&Bf[k * 256 + jhi];
        ulonglong2 cl = *(const ulonglong2*)&Bf[(k + 1) * 256 + jlo];
        ulonglong2 ch = *(const ulonglong2*)&Bf[(k + 1) * 256 + jhi];
        #pragma unroll
        for (int r = 0; r < RT; ++r) {
            float2 a = *(const float2*)&A32[(trow * RT + r) * 256 + kb + k];
            u64 ax = dup2(a.x);
            ffma2(acc[r][0], ax, bl.x); ffma2(acc[r][1], ax, bl.y);
            ffma2(acc[r][2], ax, bh.x); ffma2(acc[r][3], ax, bh.y);
            u64 ay = dup2(a.y);
            ffma2(acc[r][0], ay, cl.x); ffma2(acc[r][1], ay, cl.y);
            ffma2(acc[r][2], ay, ch.x); ffma2(acc[r][3], ay, ch.y);
        }
    }
}

// ---- main kernel ----
__global__ void __launch_bounds__(NTHREADS, 1)
mlp_hyb(const float* __restrict__ x,
        const float* __restrict__ b0, const float* __restrict__ b1,
        const float* __restrict__ u1cb, const float* __restrict__ b2,
        const float* __restrict__ u2cb, const float* __restrict__ bo,
        float* __restrict__ out)
{
    extern __shared__ __align__(1024) unsigned char sm[];
    const u32 smb = smem_u32(sm);
    const int tid = threadIdx.x, lane = tid & 31, wid = tid >> 5;
    const bool is_mma = wid < 8;

    // HMMA ids (8 warps): 2 m-tiles x 4 n-tiles, rows 0-63
    const int wm = wid & 1, wn = (wid >> 1) & 3;
    const int mrow = wm * 32, ncol = wn * 64;
    // FFMA ids (8 warps): rows 64-127
    const int ftid = tid & 255;
    const int tcol = ftid & 31, trow = ftid >> 5;
    const int jlo = 4 * tcol, jhi = 128 + 4 * tcol;

    const int r0g = (int)(((long long)blockIdx.x << 15) / NCTA) & ~7;
    const int r1g = (int)(((long long)(blockIdx.x + 1) << 15) / NCTA) & ~7;

    u32 bad[4];
    #pragma unroll
    for (int nt2 = 0; nt2 < 4; ++nt2) {
        int n0 = ncol + nt2 * 16;
        int nrow = n0 + (lane & 7) + ((lane >> 4) << 3);
        bad[nt2] = nrow * BROW + (((lane >> 3) & 1) << 4);
    }

    // cp.async piece indices: HMMA 1024 pieces, FFMA 1024 pieces per chunk
    const int i0 = tid * 2, i1 = tid * 2 + 1;
    const int p0 = i0 >> 9, n0c = (i0 >> 1) & 255, j0 = i0 & 1;
    const int p1 = i1 >> 9, n1c = (i1 >> 1) & 255, j1 = i1 & 1;

#define ISSUE_CHUNK(gg) do { \
    const int _L = (gg) >> 4, _ck = (gg) & 15, _s = (gg) & 1; \
    u32 _dh = smb + BH_OFF + _s * BBUF; \
    CPASYNC16(_dh + p0 * BPLANE + n0c * BROW + j0 * 16, \
              (const char*)&d_Bw[_L][p0][_ck][n0c][j0 * 8]); \
    CPASYNC16(_dh + p1 * BPLANE + n1c * BROW + j1 * 16, \
              (const char*)&d_Bw[_L][p1][_ck][n1c][j1 * 8]); \
    u32 _df = smb + BF_OFF + _s * 16384; \
    const char* _sf = (const char*)&d_Bf[_L][_ck][0][0]; \
    CPASYNC16(_df + tid * 32,      _sf + tid * 32); \
    CPASYNC16(_df + tid * 32 + 16, _sf + tid * 32 + 16); \
    asm volatile("cp.async.commit_group;"); \
} while (0)

    for (int sub = 0; sub < 2; ++sub) {
        const int rbase = sub ? (r0g + 128) : r0g;
        const int realf = sub ? (r1g - r0g - 128) : 128;   // total rows this subtile

        ISSUE_CHUNK(0);

        // ---- x-load: rows 0-63 -> bf16 planes; rows 64..realf-1 -> f32 ----
        #pragma unroll
        for (int it = 0; it < 8; ++it) {
            int idx = it * NTHREADS + tid;                  // 0..4095
            int row = idx >> 6, c0 = (idx & 63) * 4;        // rows 0..63 always real
            float4 f = __ldg((const float4*)(x + (size_t)(rbase + row) * DD + c0));
            u32 h0, l0, h1, l1;
            split2(f.x, f.y, h0, l0);
            split2(f.z, f.w, h1, l1);
            int off = aoff(row, c0);
            *(uint2*)(sm + A_HI + off) = make_uint2(h0, h1);
            *(uint2*)(sm + A_LO + off) = make_uint2(l0, l1);
        }
        {
            const int fr = sub ? 32 : 64;                   // f32 rows staged
            for (int it = 0; it < fr / 8; ++it) {
                int idx = it * NTHREADS + tid;
                int row = idx >> 6, c0 = (idx & 63) * 4;    // A32-local row
                float4 f = make_float4(0.f, 0.f, 0.f, 0.f);
                if (64 + row < realf)
                    f = __ldg((const float4*)(x + (size_t)(rbase + 64 + row) * DD + c0));
                *(float4*)(sm + AF32 + (row * 256 + c0) * 4) = f;
            }
        }

        for (int L = 0; L < 6; ++L) {
            union Acc { float h[2][8][4]; u64 f[8][4]; } A;
            #pragma unroll
            for (int r = 0; r < 8; ++r)
                #pragma unroll
                for (int c = 0; c < 4; ++c) A.f[r][c] = 0ull;

            for (int ck = 0; ck < 16; ++ck) {
                const int g = L * 16 + ck;
                asm volatile("cp.async.wait_group 0;");
                __syncthreads();                 // chunk g visible; chunk g-1 retired
                if (g + 1 < 96) ISSUE_CHUNK(g + 1);   // into slot retired by the sync

                if (is_mma) {
                    const u32 bb = smb + BH_OFF + (g & 1) * BBUF;
                    const int au = ck * 2 + (lane >> 4);
                    u32 bh[16], ah[2][4];
                    #pragma unroll
                    for (int nt2 = 0; nt2 < 4; ++nt2)
                        LDSM4(&bh[nt2 * 4], bb + bad[nt2]);
                    #pragma unroll
                    for (int mt = 0; mt < 2; ++mt) {
                        int arow = mrow + mt * 16 + (lane & 15);
                        u32 abase = arow * 512 + (((au ^ (arow & 7)) << 4));
                        LDSM4(ah[mt], smb + A_HI + abase);
                    }
                    #pragma unroll
                    for (int mt = 0; mt < 2; ++mt)
                        #pragma unroll
                        for (int j = 0; j < 8; ++j)
                            MMA(A.h[mt][j], ah[mt], bh[2 * j], bh[2 * j + 1]);
                    u32 bl[16], al[2][4];
                    #pragma unroll
                    for (int nt2 = 0; nt2 < 4; ++nt2)
                        LDSM4(&bl[nt2 * 4], bb + BPLANE + bad[nt2]);
                    #pragma unroll
                    for (int mt = 0; mt < 2; ++mt) {
                        int arow = mrow + mt * 16 + (lane & 15);
                        u32 abase = arow * 512 + (((au ^ (arow & 7)) << 4));
                        LDSM4(al[mt], smb + A_LO + abase);
                    }
                    #pragma unroll
                    for (int mt = 0; mt < 2; ++mt)
                        #pragma unroll
                        for (int j = 0; j < 8; ++j)
                            MMA(A.h[mt][j], ah[mt], bl[2 * j], bl[2 * j + 1]);
                    #pragma unroll
                    for (int mt = 0; mt < 2; ++mt)
                        #pragma unroll
                        for (int j = 0; j < 8; ++j)
                            MMA(A.h[mt][j], al[mt], bh[2 * j], bh[2 * j + 1]);
                } else {
                    if (sub == 0)
                        ffma_chunk<8>(sm, A.f, g & 1, ck * 16, trow, jlo, jhi);
                    else
                        ffma_chunk<4>(sm, A.f, g & 1, ck * 16, trow, jlo, jhi);
                }
            }

            __syncthreads();           // all compute done before A overwrite

            // ---- epilogue ----
            const float* bias;
            switch (L) {
                case 0: bias = b0;   break;
                case 1: bias = b1;   break;
                case 2: bias = u1cb; break;
                case 3: bias = b2;   break;
                case 4: bias = u2cb; break;
                default: bias = bo;  break;
            }
            const float* pv = d_p + ((L == 2) ? 0 : 256);
            const bool ut = (L == 2 || L == 4);

            if (is_mma) {
                const int r1 = mrow + (lane >> 2);
                #pragma unroll
                for (int mt = 0; mt < 2; ++mt) {
                    #pragma unroll
                    for (int j = 0; j < 8; ++j) {
                        int col = ncol + j * 8 + (lane & 3) * 2;
                        float2 bv = __ldg((const float2*)&bias[col]);
                        float v0 = A.h[mt][j][0] + bv.x, v1 = A.h[mt][j][1] + bv.y;
                        float v2 = A.h[mt][j][2] + bv.x, v3 = A.h[mt][j][3] + bv.y;
                        if (ut) {
                            float2 pp = __ldg((const float2*)&pv[col]);
                            v0 = fast_tanh(v0 + pp.x); v1 = fast_tanh(v1 + pp.y);
                            v2 = fast_tanh(v2 + pp.x); v3 = fast_tanh(v3 + pp.y);
                        } else {
                            v0 = fmaxf(v0, 0.f); v1 = fmaxf(v1, 0.f);
                            v2 = fmaxf(v2, 0.f); v3 = fmaxf(v3, 0.f);
                        }
                        int ra = r1 + mt * 16, rb = ra + 8;   // rows 0..63, always real
                        if (L == 5) {
                            *(float2*)(out + (size_t)(rbase + ra) * DD + col)
                                = make_float2(v0, v1);
                            *(float2*)(out + (size_t)(rbase + rb) * DD + col)
                                = make_float2(v2, v3);
                        } else {
                            u32 h, l;
                            split2(v0, v1, h, l);
                            int oa = aoff(ra, col);
                            *(u32*)(sm + A_HI + oa) = h;
                            *(u32*)(sm + A_LO + oa) = l;
                            split2(v2, v3, h, l);
                            int ob = aoff(rb, col);
                            *(u32*)(sm + A_HI + ob) = h;
                            *(u32*)(sm + A_LO + ob) = l;
                        }
                    }
                }
            } else {
                const int rt = sub ? 4 : 8;
                float4 bl4 = __ldg((const float4*)&bias[jlo]);
                float4 bh4 = __ldg((const float4*)&bias[jhi]);
                float4 pl4 = make_float4(0.f, 0.f, 0.f, 0.f), ph4 = pl4;
                if (ut) {
                    pl4 = __ldg((const float4*)&pv[jlo]);
                    ph4 = __ldg((const float4*)&pv[jhi]);
                }
                for (int r = 0; r < rt; ++r) {
                    int lrow = trow * rt + r;              // A32-local row
                    float2 u0 = unpack2(A.f[r][0]), u1v = unpack2(A.f[r][1]);
                    float2 u2 = unpack2(A.f[r][2]), u3 = unpack2(A.f[r][3]);
                    float4 lo = make_float4(u0.x + bl4.x, u0.y + bl4.y,
                                            u1v.x + bl4.z, u1v.y + bl4.w);
                    float4 hi = make_float4(u2.x + bh4.x, u2.y + bh4.y,
                                            u3.x + bh4.z, u3.y + bh4.w);
                    if (ut) {
                        lo.x = fast_tanh(lo.x + pl4.x); lo.y = fast_tanh(lo.y + pl4.y);
                        lo.z = fast_tanh(lo.z + pl4.z); lo.w = fast_tanh(lo.w + pl4.w);
                        hi.x = fast_tanh(hi.x + ph4.x); hi.y = fast_tanh(hi.y + ph4.y);
                        hi.z = fast_tanh(hi.z + ph4.z); hi.w = fast_tanh(hi.w + ph4.w);
                    } else {
                        lo.x = fmaxf(lo.x, 0.f); lo.y = fmaxf(lo.y, 0.f);
                        lo.z = fmaxf(lo.z, 0.f); lo.w = fmaxf(lo.w, 0.f);
                        hi.x = fmaxf(hi.x, 0.f); hi.y = fmaxf(hi.y, 0.f);
                        hi.z = fmaxf(hi.z, 0.f); hi.w = fmaxf(hi.w, 0.f);
                    }
                    if (L == 5) {
                        if (64 + lrow < realf) {
                            float* orow = out + (size_t)(rbase + 64 + lrow) * DD;
                            *(float4*)(orow + jlo) = lo;
                            *(float4*)(orow + jhi) = hi;
                        }
                    } else {
                        float* arow = (float*)(sm + AF32) + lrow * 256;
                        *(float4*)(arow + jlo) = lo;
                        *(float4*)(arow + jhi) = hi;
                    }
                }
            }
            // next chunk-loop's first __syncthreads orders epilogue writes vs reads
        }
    }
#undef ISSUE_CHUNK
}

extern "C" void kernel_launch(void* const* d_in, const int* in_sizes, int n_in,
                              void* d_out, int out_size) {
    (void)in_sizes; (void)n_in; (void)out_size;
    const float* x    = (const float*)d_in[0];
    const float* w0   = (const float*)d_in[1];
    const float* b0   = (const float*)d_in[2];
    const float* w1   = (const float*)d_in[3];
    const float* b1   = (const float*)d_in[4];
    const float* u1w  = (const float*)d_in[5];
    const float* u1cw = (const float*)d_in[6];
    const float* u1cb = (const float*)d_in[7];
    const float* w2   = (const float*)d_in[8];
    const float* b2   = (const float*)d_in[9];
    const float* u2w  = (const float*)d_in[10];
    const float* u2cw = (const float*)d_in[11];
    const float* u2cb = (const float*)d_in[12];
    const float* wo   = (const float*)d_in[13];
    const float* bo   = (const float*)d_in[14];
    float* out = (float*)d_out;

    cudaFuncSetAttribute(mlp_hyb, cudaFuncAttributeMaxDynamicSharedMemorySize, SMEM_TOTAL);

    prep<<<1538, 256>>>(w0, w1, u1cw, w2, u2cw, wo, u1w, u2w);
    mlp_hyb<<<NCTA, NTHREADS, SMEM_TOTAL>>>(x, b0, b1, u1cb, b2, u2cb, bo, out);
}

// round 13
// speedup vs baseline: 3.9440x; 3.9440x over previous
#include <cuda_runtime.h>
#include <cuda_fp16.h>
#include <cstdint>

typedef uint32_t u32; typedef unsigned short u16;

#define DD 256
#define NCTA 148
#define NTHREADS 512

// ---- smem byte offsets ----
#define A_HI 0                      // [128][256] fp16 hi plane, swizzled, 64KB
#define A_LO 65536                  // fp16 lo plane, 64KB
#define BW_OFF 131072               // 3 slots x [256 n x 48B] single fp16 plane
#define BROW 48
#define BPLANE (256 * BROW)         // 12288 per slot
#define BIAS_OFF (BW_OFF + 3 * BPLANE)      // 167936 (6*256 floats)
#define PV_OFF   (BIAS_OFF + 6 * 256 * 4)   // 174080 (512 floats)
#define SMEM_TOTAL (PV_OFF + 512 * 4)       // 176128 (172 KB)

// ---- device scratch ----
__device__ float d_p[2 * DD];
// [layer][k-chunk][n][k-within-chunk]  (single fp16 plane)
__device__ __align__(16) __half d_Bw[6][16][256][16];

// ---- helpers ----
__device__ __forceinline__ u32 smem_u32(const void* p) {
    u32 a;
    asm("{ .reg .u64 t; cvta.to.shared.u64 t, %1; cvt.u32.u64 %0, t; }" : "=r"(a) : "l"(p));
    return a;
}
__device__ __forceinline__ float fast_tanh(float x) {
    float e, r;
    asm("ex2.approx.f32 %0, %1;" : "=f"(e) : "f"(x * 2.8853900817779268f));
    asm("rcp.approx.f32 %0, %1;" : "=f"(r) : "f"(e + 1.0f));
    return 1.0f - 2.0f * r;
}
// fp16 hi/lo split of two floats, packed as fp16x2 words
__device__ __forceinline__ void split2h(float a, float b, u32& h, u32& l) {
    __half ha = __float2half_rn(a), hb = __float2half_rn(b);
    float fa = __half2float(ha),    fb = __half2float(hb);
    __half la = __float2half_rn(a - fa), lb = __float2half_rn(b - fb);
    h = ((u32)__half_as_ushort(hb) << 16) | __half_as_ushort(ha);
    l = ((u32)__half_as_ushort(lb) << 16) | __half_as_ushort(la);
}
// swizzled byte offset into an A plane: row stride 512B, 16B units XOR'd by row
__device__ __forceinline__ int aoff(int row, int col) {
    return row * 512 + ((((col >> 3) ^ (row & 7)) << 4) | ((col & 7) << 1));
}

#define LDSM4(r, addr) \
    asm volatile("ldmatrix.sync.aligned.m8n8.x4.shared.b16 {%0,%1,%2,%3}, [%4];" \
        : "=r"((r)[0]), "=r"((r)[1]), "=r"((r)[2]), "=r"((r)[3]) : "r"(addr))
#define MMA(d, a, b0, b1) \
    asm volatile("mma.sync.aligned.m16n8k16.row.col.f32.f16.f16.f32 " \
        "{%0,%1,%2,%3}, {%4,%5,%6,%7}, {%8,%9}, {%0,%1,%2,%3};" \
        : "+f"((d)[0]), "+f"((d)[1]), "+f"((d)[2]), "+f"((d)[3]) \
        : "r"((a)[0]), "r"((a)[1]), "r"((a)[2]), "r"((a)[3]), "r"(b0), "r"(b1))
#define CPASYNC16(dst, src) \
    asm volatile("cp.async.cg.shared.global [%0], [%1], 16;" :: "r"(dst), "l"(src))

// ---- fused prologue: weight fp16 reorder + p-vector ----
__global__ void prep(const float* __restrict__ w0, const float* __restrict__ w1,
                     const float* __restrict__ u1cw, const float* __restrict__ w2,
                     const float* __restrict__ u2cw, const float* __restrict__ wo,
                     const float* __restrict__ u1w, const float* __restrict__ u2w) {
    int b = blockIdx.x;
    if (b < 1536) {
        int L = b >> 8, n = b & 255, k = threadIdx.x;
        const float* W; bool direct;
        switch (L) {
            case 0: W = w0;   direct = false; break;
            case 1: W = w1;   direct = false; break;
            case 2: W = u1cw; direct = true;  break;
            case 3: W = w2;   direct = false; break;
            case 4: W = u2cw; direct = true;  break;
            default: W = wo;  direct = false; break;
        }
        // B[n][k]: layers computing h @ W^T read W[n][k]; direct (h @ W) reads W[k][n]
        float wv = direct ? W[k * DD + n] : W[n * DD + k];
        d_Bw[L][k >> 4][n][k & 15] = __float2half_rn(wv);
    } else {
        int t = (b - 1536) * 256 + threadIdx.x;    // 0..511
        const float* w = (t < DD) ? u1w : u2w;
        int j = t & (DD - 1);
        float prod = 1.0f / (float)DD;
        #pragma unroll
        for (int d = 0; d < 9; ++d)
            #pragma unroll
            for (int g = 0; g < 3; ++g) {
                float c = cosf(w[(d * DD + j) * DD + g]);
                prod *= c * c;
            }
        d_p[t] = prod;
    }
}

// ---- main kernel ----
__global__ void __launch_bounds__(NTHREADS, 1)
mlp_mma(const float* __restrict__ x,
        const float* __restrict__ b0, const float* __restrict__ b1,
        const float* __restrict__ u1cb, const float* __restrict__ b2,
        const float* __restrict__ u2cb, const float* __restrict__ bo,
        float* __restrict__ out)
{
    extern __shared__ __align__(1024) unsigned char sm[];
    float* smf = (float*)sm;
    const u32 smb = smem_u32(sm);
    const int tid = threadIdx.x, lane = tid & 31, wid = tid >> 5;
    const int wm = wid & 3, wn = wid >> 2;
    const int mrow = wm * 32, ncol = wn * 64;

    // ---- stage biases and p ----
    if (tid < 256) {
        const float* bs[6] = { b0, b1, u1cb, b2, u2cb, bo };
        #pragma unroll
        for (int L = 0; L < 6; ++L) smf[BIAS_OFF / 4 + L * 256 + tid] = bs[L][tid];
        smf[PV_OFF / 4 + tid]       = d_p[tid];
        smf[PV_OFF / 4 + 256 + tid] = d_p[256 + tid];
    }

    // row range for this CTA (8-aligned, balanced over 148 CTAs)
    const int r0g = (int)(((long long)blockIdx.x << 15) / NCTA) & ~7;
    const int r1g = (int)(((long long)(blockIdx.x + 1) << 15) / NCTA) & ~7;

    // precomputed B ldmatrix base offsets for this warp
    u32 bad[4];
    #pragma unroll
    for (int nt2 = 0; nt2 < 4; ++nt2) {
        int n0 = ncol + nt2 * 16;
        int nrow = n0 + (lane & 7) + ((lane >> 4) << 3);
        bad[nt2] = nrow * BROW + (((lane >> 3) & 1) << 4);
    }

    // per-thread cp.async piece (ONE 16B copy per thread per chunk: 256n x 32B)
    const int cn = tid >> 1, cj = tid & 1;

    for (int sub = 0; sub < 2; ++sub) {
        const int rbase = r0g + sub * 128;
        const int H     = sub ? 96 : 128;
        const int real  = sub ? (r1g - r0g - 128) : 128;
        const bool act  = (sub == 0) | (wm < 3);

        // ---- prime ring: issue chunks 0 and 1 ----
        #pragma unroll
        for (int pg = 0; pg < 2; ++pg) {
            u32 dst = smb + BW_OFF + pg * BPLANE + cn * BROW + cj * 16;
            CPASYNC16(dst, (const char*)&d_Bw[0][pg][cn][cj * 8]);
            asm volatile("cp.async.commit_group;");
        }

        // ---- load x tile (zero-padded), split to fp16 hi/lo planes ----
        {
            const int iters = (H * 64) / NTHREADS;     // 16 or 12
            for (int it = 0; it < iters; ++it) {
                int idx = it * NTHREADS + tid;
                int row = idx >> 6, c0 = (idx & 63) * 4;
                float4 f = make_float4(0.f, 0.f, 0.f, 0.f);
                if (row < real)
                    f = __ldg((const float4*)(x + (size_t)(rbase + row) * DD + c0));
                u32 h0, l0, h1, l1;
                split2h(f.x, f.y, h0, l0);
                split2h(f.z, f.w, h1, l1);
                int off = aoff(row, c0);
                *(uint2*)(sm + A_HI + off) = make_uint2(h0, h1);
                *(uint2*)(sm + A_LO + off) = make_uint2(l0, l1);
            }
        }

        for (int L = 0; L < 6; ++L) {
            float acc[2][8][4];
            #pragma unroll
            for (int mt = 0; mt < 2; ++mt)
                #pragma unroll
                for (int j = 0; j < 8; ++j)
                    #pragma unroll
                    for (int q = 0; q < 4; ++q) acc[mt][j][q] = 0.f;

            for (int ck = 0; ck < 16; ++ck) {
                const int g = L * 16 + ck;
                if (g < 95) asm volatile("cp.async.wait_group 1;");
                else        asm volatile("cp.async.wait_group 0;");
                __syncthreads();
                // refill slot (g+2)%3 (retired by the barrier above)
                if (g + 2 < 96) {
                    const int g2 = g + 2;
                    const int nL = g2 >> 4, nck = g2 & 15;
                    u32 dst = smb + BW_OFF + (g2 % 3) * BPLANE + cn * BROW + cj * 16;
                    CPASYNC16(dst, (const char*)&d_Bw[nL][nck][cn][cj * 8]);
                    asm volatile("cp.async.commit_group;");
                }

                if (act) {
                    const u32 bb = smb + BW_OFF + (g % 3) * BPLANE;
                    const int au = ck * 2 + (lane >> 4);

                    u32 bh[16], ah[2][4], al[2][4];
                    #pragma unroll
                    for (int nt2 = 0; nt2 < 4; ++nt2)
                        LDSM4(&bh[nt2 * 4], bb + bad[nt2]);
                    #pragma unroll
                    for (int mt = 0; mt < 2; ++mt) {
                        int arow = mrow + mt * 16 + (lane & 15);
                        u32 abase = arow * 512 + (((au ^ (arow & 7)) << 4));
                        LDSM4(ah[mt], smb + A_HI + abase);
                    }
                    // pass 1: A_hi x B
                    #pragma unroll
                    for (int mt = 0; mt < 2; ++mt)
                        #pragma unroll
                        for (int j = 0; j < 8; ++j)
                            MMA(acc[mt][j], ah[mt], bh[2 * j], bh[2 * j + 1]);
                    #pragma unroll
                    for (int mt = 0; mt < 2; ++mt) {
                        int arow = mrow + mt * 16 + (lane & 15);
                        u32 abase = arow * 512 + (((au ^ (arow & 7)) << 4));
                        LDSM4(al[mt], smb + A_LO + abase);
                    }
                    // pass 2: A_lo x B
                    #pragma unroll
                    for (int mt = 0; mt < 2; ++mt)
                        #pragma unroll
                        for (int j = 0; j < 8; ++j)
                            MMA(acc[mt][j], al[mt], bh[2 * j], bh[2 * j + 1]);
                }
            }

            __syncthreads();       // all compute done before A overwrite

            // ---- epilogue: bias + activation ----
            if (act) {
                const float* bias = smf + BIAS_OFF / 4 + L * 256;
                const float* pv   = smf + PV_OFF / 4 + ((L == 2) ? 0 : 256);
                const bool ut = (L == 2 || L == 4);
                const int r1 = mrow + (lane >> 2);
                #pragma unroll
                for (int mt = 0; mt < 2; ++mt) {
                    #pragma unroll
                    for (int j = 0; j < 8; ++j) {
                        int col = ncol + j * 8 + (lane & 3) * 2;
                        float bx = bias[col], by = bias[col + 1];
                        float v0 = acc[mt][j][0] + bx, v1 = acc[mt][j][1] + by;
                        float v2 = acc[mt][j][2] + bx, v3 = acc[mt][j][3] + by;
                        if (ut) {
                            float px = pv[col], py = pv[col + 1];
                            v0 = fast_tanh(v0 + px); v1 = fast_tanh(v1 + py);
                            v2 = fast_tanh(v2 + px); v3 = fast_tanh(v3 + py);
                        } else {
                            v0 = fmaxf(v0, 0.f); v1 = fmaxf(v1, 0.f);
                            v2 = fmaxf(v2, 0.f); v3 = fmaxf(v3, 0.f);
                        }
                        int ra = r1 + mt * 16, rb = ra + 8;
                        if (L == 5) {
                            if (ra < real) {
                                *(float2*)(out + (size_t)(rbase + ra) * DD + col)
                                    = make_float2(v0, v1);
                            }
                            if (rb < real) {
                                *(float2*)(out + (size_t)(rbase + rb) * DD + col)
                                    = make_float2(v2, v3);
                            }
                        } else {
                            u32 h, l;
                            split2h(v0, v1, h, l);
                            int oa = aoff(ra, col);
                            *(u32*)(sm + A_HI + oa) = h;
                            *(u32*)(sm + A_LO + oa) = l;
                            split2h(v2, v3, h, l);
                            int ob = aoff(rb, col);
                            *(u32*)(sm + A_HI + ob) = h;
                            *(u32*)(sm + A_LO + ob) = l;
                        }
                    }
                }
            }
            // next chunk-loop's first __syncthreads orders epilogue writes vs reads
        }
    }
}

extern "C" void kernel_launch(void* const* d_in, const int* in_sizes, int n_in,
                              void* d_out, int out_size) {
    (void)in_sizes; (void)n_in; (void)out_size;
    const float* x    = (const float*)d_in[0];
    const float* w0   = (const float*)d_in[1];
    const float* b0   = (const float*)d_in[2];
    const float* w1   = (const float*)d_in[3];
    const float* b1   = (const float*)d_in[4];
    const float* u1w  = (const float*)d_in[5];
    const float* u1cw = (const float*)d_in[6];
    const float* u1cb = (const float*)d_in[7];
    const float* w2   = (const float*)d_in[8];
    const float* b2   = (const float*)d_in[9];
    const float* u2w  = (const float*)d_in[10];
    const float* u2cw = (const float*)d_in[11];
    const float* u2cb = (const float*)d_in[12];
    const float* wo   = (const float*)d_in[13];
    const float* bo   = (const float*)d_in[14];
    float* out = (float*)d_out;

    cudaFuncSetAttribute(mlp_mma, cudaFuncAttributeMaxDynamicSharedMemorySize, SMEM_TOTAL);

    prep<<<1538, 256>>>(w0, w1, u1cw, w2, u2cw, wo, u1w, u2w);
    mlp_mma<<<NCTA, NTHREADS, SMEM_TOTAL>>>(x, b0, b1, u1cb, b2, u2cb, bo, out);
}

// round 14
// speedup vs baseline: 4.1510x; 1.0525x over previous
#include <cuda_runtime.h>
#include <cuda_fp16.h>
#include <cstdint>

typedef uint32_t u32; typedef unsigned short u16;

#define DD 256
#define NCTA 296
#define NTHREADS 256

// ---- smem byte offsets (per CTA: 108 KB -> 2 CTAs/SM) ----
#define A_HI 0                      // [64][256] fp16 hi plane, swizzled, 32KB
#define A_LO 32768                  // fp16 lo plane, 32KB
#define BW_OFF 65536                // 3 slots x [256 n x 48B] single fp16 plane
#define BROW 48
#define BPLANE (256 * BROW)         // 12288 per slot
#define BIAS_OFF (BW_OFF + 3 * BPLANE)      // 102400 (6*256 floats)
#define PV_OFF   (BIAS_OFF + 6 * 256 * 4)   // 108544 (512 floats)
#define SMEM_TOTAL (PV_OFF + 512 * 4)       // 110592 (108 KB)

// ---- device scratch ----
__device__ float d_p[2 * DD];
// [layer][k-chunk][n][k-within-chunk]  (single fp16 plane)
__device__ __align__(16) __half d_Bw[6][16][256][16];

// ---- helpers ----
__device__ __forceinline__ u32 smem_u32(const void* p) {
    u32 a;
    asm("{ .reg .u64 t; cvta.to.shared.u64 t, %1; cvt.u32.u64 %0, t; }" : "=r"(a) : "l"(p));
    return a;
}
__device__ __forceinline__ float fast_tanh(float x) {
    float e, r;
    asm("ex2.approx.f32 %0, %1;" : "=f"(e) : "f"(x * 2.8853900817779268f));
    asm("rcp.approx.f32 %0, %1;" : "=f"(r) : "f"(e + 1.0f));
    return 1.0f - 2.0f * r;
}
// fp16 hi/lo split of two floats, packed as fp16x2 words
__device__ __forceinline__ void split2h(float a, float b, u32& h, u32& l) {
    __half ha = __float2half_rn(a), hb = __float2half_rn(b);
    float fa = __half2float(ha),    fb = __half2float(hb);
    __half la = __float2half_rn(a - fa), lb = __float2half_rn(b - fb);
    h = ((u32)__half_as_ushort(hb) << 16) | __half_as_ushort(ha);
    l = ((u32)__half_as_ushort(lb) << 16) | __half_as_ushort(la);
}
// swizzled byte offset into an A plane: row stride 512B, 16B units XOR'd by row
__device__ __forceinline__ int aoff(int row, int col) {
    return row * 512 + ((((col >> 3) ^ (row & 7)) << 4) | ((col & 7) << 1));
}

#define LDSM4(r, addr) \
    asm volatile("ldmatrix.sync.aligned.m8n8.x4.shared.b16 {%0,%1,%2,%3}, [%4];" \
        : "=r"((r)[0]), "=r"((r)[1]), "=r"((r)[2]), "=r"((r)[3]) : "r"(addr))
#define MMA(d, a, b0, b1) \
    asm volatile("mma.sync.aligned.m16n8k16.row.col.f32.f16.f16.f32 " \
        "{%0,%1,%2,%3}, {%4,%5,%6,%7}, {%8,%9}, {%0,%1,%2,%3};" \
        : "+f"((d)[0]), "+f"((d)[1]), "+f"((d)[2]), "+f"((d)[3]) \
        : "r"((a)[0]), "r"((a)[1]), "r"((a)[2]), "r"((a)[3]), "r"(b0), "r"(b1))
#define CPASYNC16(dst, src) \
    asm volatile("cp.async.cg.shared.global [%0], [%1], 16;" :: "r"(dst), "l"(src))

// ---- fused prologue: weight fp16 reorder + p-vector ----
__global__ void prep(const float* __restrict__ w0, const float* __restrict__ w1,
                     const float* __restrict__ u1cw, const float* __restrict__ w2,
                     const float* __restrict__ u2cw, const float* __restrict__ wo,
                     const float* __restrict__ u1w, const float* __restrict__ u2w) {
    int b = blockIdx.x;
    if (b < 1536) {
        int L = b >> 8, n = b & 255, k = threadIdx.x;
        const float* W; bool direct;
        switch (L) {
            case 0: W = w0;   direct = false; break;
            case 1: W = w1;   direct = false; break;
            case 2: W = u1cw; direct = true;  break;
            case 3: W = w2;   direct = false; break;
            case 4: W = u2cw; direct = true;  break;
            default: W = wo;  direct = false; break;
        }
        // B[n][k]: layers computing h @ W^T read W[n][k]; direct (h @ W) reads W[k][n]
        float wv = direct ? W[k * DD + n] : W[n * DD + k];
        d_Bw[L][k >> 4][n][k & 15] = __float2half_rn(wv);
    } else {
        int t = (b - 1536) * 256 + threadIdx.x;    // 0..511
        const float* w = (t < DD) ? u1w : u2w;
        int j = t & (DD - 1);
        float prod = 1.0f / (float)DD;
        #pragma unroll
        for (int d = 0; d < 9; ++d)
            #pragma unroll
            for (int g = 0; g < 3; ++g) {
                float c = cosf(w[(d * DD + j) * DD + g]);
                prod *= c * c;
            }
        d_p[t] = prod;
    }
}

// ---- main kernel: 64-row tiles, 2 CTAs per SM ----
__global__ void __launch_bounds__(NTHREADS, 2)
mlp_mma(const float* __restrict__ x,
        const float* __restrict__ b0, const float* __restrict__ b1,
        const float* __restrict__ u1cb, const float* __restrict__ b2,
        const float* __restrict__ u2cb, const float* __restrict__ bo,
        float* __restrict__ out)
{
    extern __shared__ __align__(1024) unsigned char sm[];
    float* smf = (float*)sm;
    const u32 smb = smem_u32(sm);
    const int tid = threadIdx.x, lane = tid & 31, wid = tid >> 5;
    const int wm = wid & 1, wn = wid >> 1;       // 2 m-tiles x 4 n-slabs
    const int mrow = wm * 32, ncol = wn * 64;

    // ---- stage biases and p ----
    {
        const float* bs[6] = { b0, b1, u1cb, b2, u2cb, bo };
        #pragma unroll
        for (int L = 0; L < 6; ++L) smf[BIAS_OFF / 4 + L * 256 + tid] = bs[L][tid];
        smf[PV_OFF / 4 + tid]       = d_p[tid];
        smf[PV_OFF / 4 + 256 + tid] = d_p[256 + tid];
    }

    // row range for this CTA (8-aligned, balanced over 296 CTAs)
    const int r0g = (int)(((long long)blockIdx.x << 15) / NCTA) & ~7;
    const int r1g = (int)(((long long)(blockIdx.x + 1) << 15) / NCTA) & ~7;

    // precomputed B ldmatrix base offsets for this warp
    u32 bad[4];
    #pragma unroll
    for (int nt2 = 0; nt2 < 4; ++nt2) {
        int n0 = ncol + nt2 * 16;
        int nrow = n0 + (lane & 7) + ((lane >> 4) << 3);
        bad[nt2] = nrow * BROW + (((lane >> 3) & 1) << 4);
    }

    // per-thread cp.async pieces (512 x 16B per chunk over 256 threads = 2 each)
    const int cn0 = tid >> 1, cj0 = tid & 1;       // piece tid
    const int cn1 = cn0 + 128, cj1 = cj0;          // piece tid+256

    for (int sub = 0; sub < 2; ++sub) {
        const int rbase = r0g + sub * 64;
        const int real  = sub ? (r1g - r0g - 64) : 64;   // sub1: 40..56

        // ---- prime ring: issue chunks 0 and 1 ----
        #pragma unroll
        for (int pg = 0; pg < 2; ++pg) {
            u32 dst = smb + BW_OFF + pg * BPLANE;
            CPASYNC16(dst + cn0 * BROW + cj0 * 16, (const char*)&d_Bw[0][pg][cn0][cj0 * 8]);
            CPASYNC16(dst + cn1 * BROW + cj1 * 16, (const char*)&d_Bw[0][pg][cn1][cj1 * 8]);
            asm volatile("cp.async.commit_group;");
        }

        // ---- load x tile (zero-padded), split to fp16 hi/lo planes ----
        #pragma unroll 4
        for (int it = 0; it < 16; ++it) {
            int idx = it * NTHREADS + tid;           // 0..4095
            int row = idx >> 6, c0 = (idx & 63) * 4;
            float4 f = make_float4(0.f, 0.f, 0.f, 0.f);
            if (row < real)
                f = __ldg((const float4*)(x + (size_t)(rbase + row) * DD + c0));
            u32 h0, l0, h1, l1;
            split2h(f.x, f.y, h0, l0);
            split2h(f.z, f.w, h1, l1);
            int off = aoff(row, c0);
            *(uint2*)(sm + A_HI + off) = make_uint2(h0, h1);
            *(uint2*)(sm + A_LO + off) = make_uint2(l0, l1);
        }

        for (int L = 0; L < 6; ++L) {
            float acc[2][8][4];
            #pragma unroll
            for (int mt = 0; mt < 2; ++mt)
                #pragma unroll
                for (int j = 0; j < 8; ++j)
                    #pragma unroll
                    for (int q = 0; q < 4; ++q) acc[mt][j][q] = 0.f;

            for (int ck = 0; ck < 16; ++ck) {
                const int g = L * 16 + ck;
                if (g < 95) asm volatile("cp.async.wait_group 1;");
                else        asm volatile("cp.async.wait_group 0;");
                __syncthreads();
                // refill slot (g+2)%3 (retired by the barrier above)
                if (g + 2 < 96) {
                    const int g2 = g + 2;
                    const int nL = g2 >> 4, nck = g2 & 15;
                    u32 dst = smb + BW_OFF + (g2 % 3) * BPLANE;
                    CPASYNC16(dst + cn0 * BROW + cj0 * 16,
                              (const char*)&d_Bw[nL][nck][cn0][cj0 * 8]);
                    CPASYNC16(dst + cn1 * BROW + cj1 * 16,
                              (const char*)&d_Bw[nL][nck][cn1][cj1 * 8]);
                    asm volatile("cp.async.commit_group;");
                }

                {
                    const u32 bb = smb + BW_OFF + (g % 3) * BPLANE;
                    const int au = ck * 2 + (lane >> 4);

                    u32 bh[16], ah[2][4], al[2][4];
                    #pragma unroll
                    for (int nt2 = 0; nt2 < 4; ++nt2)
                        LDSM4(&bh[nt2 * 4], bb + bad[nt2]);
                    #pragma unroll
                    for (int mt = 0; mt < 2; ++mt) {
                        int arow = mrow + mt * 16 + (lane & 15);
                        u32 abase = arow * 512 + (((au ^ (arow & 7)) << 4));
                        LDSM4(ah[mt], smb + A_HI + abase);
                    }
                    // pass 1: A_hi x B
                    #pragma unroll
                    for (int mt = 0; mt < 2; ++mt)
                        #pragma unroll
                        for (int j = 0; j < 8; ++j)
                            MMA(acc[mt][j], ah[mt], bh[2 * j], bh[2 * j + 1]);
                    #pragma unroll
                    for (int mt = 0; mt < 2; ++mt) {
                        int arow = mrow + mt * 16 + (lane & 15);
                        u32 abase = arow * 512 + (((au ^ (arow & 7)) << 4));
                        LDSM4(al[mt], smb + A_LO + abase);
                    }
                    // pass 2: A_lo x B
                    #pragma unroll
                    for (int mt = 0; mt < 2; ++mt)
                        #pragma unroll
                        for (int j = 0; j < 8; ++j)
                            MMA(acc[mt][j], al[mt], bh[2 * j], bh[2 * j + 1]);
                }
            }

            __syncthreads();       // all compute done before A overwrite

            // ---- epilogue: bias + activation ----
            {
                const float* bias = smf + BIAS_OFF / 4 + L * 256;
                const float* pv   = smf + PV_OFF / 4 + ((L == 2) ? 0 : 256);
                const bool ut = (L == 2 || L == 4);
                const int r1 = mrow + (lane >> 2);
                #pragma unroll
                for (int mt = 0; mt < 2; ++mt) {
                    #pragma unroll
                    for (int j = 0; j < 8; ++j) {
                        int col = ncol + j * 8 + (lane & 3) * 2;
                        float bx = bias[col], by = bias[col + 1];
                        float v0 = acc[mt][j][0] + bx, v1 = acc[mt][j][1] + by;
                        float v2 = acc[mt][j][2] + bx, v3 = acc[mt][j][3] + by;
                        if (ut) {
                            float px = pv[col], py = pv[col + 1];
                            v0 = fast_tanh(v0 + px); v1 = fast_tanh(v1 + py);
                            v2 = fast_tanh(v2 + px); v3 = fast_tanh(v3 + py);
                        } else {
                            v0 = fmaxf(v0, 0.f); v1 = fmaxf(v1, 0.f);
                            v2 = fmaxf(v2, 0.f); v3 = fmaxf(v3, 0.f);
                        }
                        int ra = r1 + mt * 16, rb = ra + 8;   // 0..63
                        if (L == 5) {
                            if (ra < real) {
                                *(float2*)(out + (size_t)(rbase + ra) * DD + col)
                                    = make_float2(v0, v1);
                            }
                            if (rb < real) {
                                *(float2*)(out + (size_t)(rbase + rb) * DD + col)
                                    = make_float2(v2, v3);
                            }
                        } else {
                            // padded rows carry garbage but stay row-local; never stored
                            u32 h, l;
                            split2h(v0, v1, h, l);
                            int oa = aoff(ra, col);
                            *(u32*)(sm + A_HI + oa) = h;
                            *(u32*)(sm + A_LO + oa) = l;
                            split2h(v2, v3, h, l);
                            int ob = aoff(rb, col);
                            *(u32*)(sm + A_HI + ob) = h;
                            *(u32*)(sm + A_LO + ob) = l;
                        }
                    }
                }
            }
            // next chunk-loop's first __syncthreads orders epilogue writes vs reads
        }
    }
}

extern "C" void kernel_launch(void* const* d_in, const int* in_sizes, int n_in,
                              void* d_out, int out_size) {
    (void)in_sizes; (void)n_in; (void)out_size;
    const float* x    = (const float*)d_in[0];
    const float* w0   = (const float*)d_in[1];
    const float* b0   = (const float*)d_in[2];
    const float* w1   = (const float*)d_in[3];
    const float* b1   = (const float*)d_in[4];
    const float* u1w  = (const float*)d_in[5];
    const float* u1cw = (const float*)d_in[6];
    const float* u1cb = (const float*)d_in[7];
    const float* w2   = (const float*)d_in[8];
    const float* b2   = (const float*)d_in[9];
    const float* u2w  = (const float*)d_in[10];
    const float* u2cw = (const float*)d_in[11];
    const float* u2cb = (const float*)d_in[12];
    const float* wo   = (const float*)d_in[13];
    const float* bo   = (const float*)d_in[14];
    float* out = (float*)d_out;

    cudaFuncSetAttribute(mlp_mma, cudaFuncAttributeMaxDynamicSharedMemorySize, SMEM_TOTAL);

    prep<<<1538, 256>>>(w0, w1, u1cw, w2, u2cw, wo, u1w, u2w);
    mlp_mma<<<NCTA, NTHREADS, SMEM_TOTAL>>>(x, b0, b1, u1cb, b2, u2cb, bo, out);
}

// round 15
// speedup vs baseline: 6.0678x; 1.4618x over previous
#include <cuda_runtime.h>
#include <cuda_fp16.h>
#include <cstdint>

typedef uint32_t u32; typedef unsigned short u16;

#define DD 256
#define NCTA 296
#define NTHREADS 256

// ---- smem byte offsets (per CTA: 76 KB -> 2 CTAs/SM) ----
#define A_HI 0                      // [64][256] fp16 plane, swizzled, 32KB
#define BW_OFF 32768                // 3 slots x [256 n x 48B] fp16 plane
#define BROW 48
#define BPLANE (256 * BROW)         // 12288 per slot
#define BIAS_OFF (BW_OFF + 3 * BPLANE)      // 69632 (6*256 floats)
#define PV_OFF   (BIAS_OFF + 6 * 256 * 4)   // 75776 (512 floats)
#define SMEM_TOTAL (PV_OFF + 512 * 4)       // 77824 (76 KB)

// ---- device scratch ----
__device__ float d_p[2 * DD];
// [layer][k-chunk][n][k-within-chunk]  (single fp16 plane)
__device__ __align__(16) __half d_Bw[6][16][256][16];

// ---- helpers ----
__device__ __forceinline__ u32 smem_u32(const void* p) {
    u32 a;
    asm("{ .reg .u64 t; cvta.to.shared.u64 t, %1; cvt.u32.u64 %0, t; }" : "=r"(a) : "l"(p));
    return a;
}
__device__ __forceinline__ float fast_tanh(float x) {
    float e, r;
    asm("ex2.approx.f32 %0, %1;" : "=f"(e) : "f"(x * 2.8853900817779268f));
    asm("rcp.approx.f32 %0, %1;" : "=f"(r) : "f"(e + 1.0f));
    return 1.0f - 2.0f * r;
}
// pack two floats as fp16x2 word
__device__ __forceinline__ u32 pack2h(float a, float b) {
    __half2 h = __floats2half2_rn(a, b);
    return *(u32*)&h;
}
// swizzled byte offset into the A plane: row stride 512B, 16B units XOR'd by row
__device__ __forceinline__ int aoff(int row, int col) {
    return row * 512 + ((((col >> 3) ^ (row & 7)) << 4) | ((col & 7) << 1));
}

#define LDSM4(r, addr) \
    asm volatile("ldmatrix.sync.aligned.m8n8.x4.shared.b16 {%0,%1,%2,%3}, [%4];" \
        : "=r"((r)[0]), "=r"((r)[1]), "=r"((r)[2]), "=r"((r)[3]) : "r"(addr))
#define MMA(d, a, b0, b1) \
    asm volatile("mma.sync.aligned.m16n8k16.row.col.f32.f16.f16.f32 " \
        "{%0,%1,%2,%3}, {%4,%5,%6,%7}, {%8,%9}, {%0,%1,%2,%3};" \
        : "+f"((d)[0]), "+f"((d)[1]), "+f"((d)[2]), "+f"((d)[3]) \
        : "r"((a)[0]), "r"((a)[1]), "r"((a)[2]), "r"((a)[3]), "r"(b0), "r"(b1))
#define CPASYNC16(dst, src) \
    asm volatile("cp.async.cg.shared.global [%0], [%1], 16;" :: "r"(dst), "l"(src))

// ---- fused prologue: weight fp16 reorder + p-vector ----
__global__ void prep(const float* __restrict__ w0, const float* __restrict__ w1,
                     const float* __restrict__ u1cw, const float* __restrict__ w2,
                     const float* __restrict__ u2cw, const float* __restrict__ wo,
                     const float* __restrict__ u1w, const float* __restrict__ u2w) {
    int b = blockIdx.x;
    if (b < 1536) {
        int L = b >> 8, n = b & 255, k = threadIdx.x;
        const float* W; bool direct;
        switch (L) {
            case 0: W = w0;   direct = false; break;
            case 1: W = w1;   direct = false; break;
            case 2: W = u1cw; direct = true;  break;
            case 3: W = w2;   direct = false; break;
            case 4: W = u2cw; direct = true;  break;
            default: W = wo;  direct = false; break;
        }
        // B[n][k]: layers computing h @ W^T read W[n][k]; direct (h @ W) reads W[k][n]
        float wv = direct ? W[k * DD + n] : W[n * DD + k];
        d_Bw[L][k >> 4][n][k & 15] = __float2half_rn(wv);
    } else {
        int t = (b - 1536) * 256 + threadIdx.x;    // 0..511
        const float* w = (t < DD) ? u1w : u2w;
        int j = t & (DD - 1);
        float prod = 1.0f / (float)DD;
        #pragma unroll
        for (int d = 0; d < 9; ++d)
            #pragma unroll
            for (int g = 0; g < 3; ++g) {
                float c = cosf(w[(d * DD + j) * DD + g]);
                prod *= c * c;
            }
        d_p[t] = prod;
    }
}

// ---- main kernel: 64-row tiles, single-pass fp16, 2 CTAs per SM ----
__global__ void __launch_bounds__(NTHREADS, 2)
mlp_mma(const float* __restrict__ x,
        const float* __restrict__ b0, const float* __restrict__ b1,
        const float* __restrict__ u1cb, const float* __restrict__ b2,
        const float* __restrict__ u2cb, const float* __restrict__ bo,
        float* __restrict__ out)
{
    extern __shared__ __align__(1024) unsigned char sm[];
    float* smf = (float*)sm;
    const u32 smb = smem_u32(sm);
    const int tid = threadIdx.x, lane = tid & 31, wid = tid >> 5;
    const int wm = wid & 1, wn = wid >> 1;       // 2 m-tiles x 4 n-slabs
    const int mrow = wm * 32, ncol = wn * 64;

    // ---- stage biases and p ----
    {
        const float* bs[6] = { b0, b1, u1cb, b2, u2cb, bo };
        #pragma unroll
        for (int L = 0; L < 6; ++L) smf[BIAS_OFF / 4 + L * 256 + tid] = bs[L][tid];
        smf[PV_OFF / 4 + tid]       = d_p[tid];
        smf[PV_OFF / 4 + 256 + tid] = d_p[256 + tid];
    }

    // row range for this CTA (8-aligned, balanced over 296 CTAs)
    const int r0g = (int)(((long long)blockIdx.x << 15) / NCTA) & ~7;
    const int r1g = (int)(((long long)(blockIdx.x + 1) << 15) / NCTA) & ~7;

    // precomputed B ldmatrix base offsets for this warp
    u32 bad[4];
    #pragma unroll
    for (int nt2 = 0; nt2 < 4; ++nt2) {
        int n0 = ncol + nt2 * 16;
        int nrow = n0 + (lane & 7) + ((lane >> 4) << 3);
        bad[nt2] = nrow * BROW + (((lane >> 3) & 1) << 4);
    }

    // per-thread cp.async pieces (512 x 16B per chunk over 256 threads = 2 each)
    const int cn0 = tid >> 1, cj0 = tid & 1;       // piece tid
    const int cn1 = cn0 + 128, cj1 = cj0;          // piece tid+256

    for (int sub = 0; sub < 2; ++sub) {
        const int rbase = r0g + sub * 64;
        const int real  = sub ? (r1g - r0g - 64) : 64;   // sub1: 40..56

        // ---- prime ring: issue chunks 0 and 1 ----
        #pragma unroll
        for (int pg = 0; pg < 2; ++pg) {
            u32 dst = smb + BW_OFF + pg * BPLANE;
            CPASYNC16(dst + cn0 * BROW + cj0 * 16, (const char*)&d_Bw[0][pg][cn0][cj0 * 8]);
            CPASYNC16(dst + cn1 * BROW + cj1 * 16, (const char*)&d_Bw[0][pg][cn1][cj1 * 8]);
            asm volatile("cp.async.commit_group;");
        }

        // ---- load x tile (zero-padded), round to fp16 plane ----
        #pragma unroll 4
        for (int it = 0; it < 16; ++it) {
            int idx = it * NTHREADS + tid;           // 0..4095
            int row = idx >> 6, c0 = (idx & 63) * 4;
            float4 f = make_float4(0.f, 0.f, 0.f, 0.f);
            if (row < real)
                f = __ldg((const float4*)(x + (size_t)(rbase + row) * DD + c0));
            int off = aoff(row, c0);
            *(uint2*)(sm + A_HI + off) =
                make_uint2(pack2h(f.x, f.y), pack2h(f.z, f.w));
        }

        for (int L = 0; L < 6; ++L) {
            float acc[2][8][4];
            #pragma unroll
            for (int mt = 0; mt < 2; ++mt)
                #pragma unroll
                for (int j = 0; j < 8; ++j)
                    #pragma unroll
                    for (int q = 0; q < 4; ++q) acc[mt][j][q] = 0.f;

            for (int ck = 0; ck < 16; ++ck) {
                const int g = L * 16 + ck;
                if (g < 95) asm volatile("cp.async.wait_group 1;");
                else        asm volatile("cp.async.wait_group 0;");
                __syncthreads();
                // refill slot (g+2)%3 (retired by the barrier above)
                if (g + 2 < 96) {
                    const int g2 = g + 2;
                    const int nL = g2 >> 4, nck = g2 & 15;
                    u32 dst = smb + BW_OFF + (g2 % 3) * BPLANE;
                    CPASYNC16(dst + cn0 * BROW + cj0 * 16,
                              (const char*)&d_Bw[nL][nck][cn0][cj0 * 8]);
                    CPASYNC16(dst + cn1 * BROW + cj1 * 16,
                              (const char*)&d_Bw[nL][nck][cn1][cj1 * 8]);
                    asm volatile("cp.async.commit_group;");
                }

                {
                    const u32 bb = smb + BW_OFF + (g % 3) * BPLANE;
                    const int au = ck * 2 + (lane >> 4);

                    u32 bh[16], ah[2][4];
                    #pragma unroll
                    for (int nt2 = 0; nt2 < 4; ++nt2)
                        LDSM4(&bh[nt2 * 4], bb + bad[nt2]);
                    #pragma unroll
                    for (int mt = 0; mt < 2; ++mt) {
                        int arow = mrow + mt * 16 + (lane & 15);
                        u32 abase = arow * 512 + (((au ^ (arow & 7)) << 4));
                        LDSM4(ah[mt], smb + A_HI + abase);
                    }
                    // single pass: A x B
                    #pragma unroll
                    for (int mt = 0; mt < 2; ++mt)
                        #pragma unroll
                        for (int j = 0; j < 8; ++j)
                            MMA(acc[mt][j], ah[mt], bh[2 * j], bh[2 * j + 1]);
                }
            }

            __syncthreads();       // all compute done before A overwrite

            // ---- epilogue: bias + activation ----
            {
                const float* bias = smf + BIAS_OFF / 4 + L * 256;
                const float* pv   = smf + PV_OFF / 4 + ((L == 2) ? 0 : 256);
                const bool ut = (L == 2 || L == 4);
                const int r1 = mrow + (lane >> 2);
                #pragma unroll
                for (int mt = 0; mt < 2; ++mt) {
                    #pragma unroll
                    for (int j = 0; j < 8; ++j) {
                        int col = ncol + j * 8 + (lane & 3) * 2;
                        float bx = bias[col], by = bias[col + 1];
                        float v0 = acc[mt][j][0] + bx, v1 = acc[mt][j][1] + by;
                        float v2 = acc[mt][j][2] + bx, v3 = acc[mt][j][3] + by;
                        if (ut) {
                            float px = pv[col], py = pv[col + 1];
                            v0 = fast_tanh(v0 + px); v1 = fast_tanh(v1 + py);
                            v2 = fast_tanh(v2 + px); v3 = fast_tanh(v3 + py);
                        } else {
                            v0 = fmaxf(v0, 0.f); v1 = fmaxf(v1, 0.f);
                            v2 = fmaxf(v2, 0.f); v3 = fmaxf(v3, 0.f);
                        }
                        int ra = r1 + mt * 16, rb = ra + 8;   // 0..63
                        if (L == 5) {
                            if (ra < real) {
                                *(float2*)(out + (size_t)(rbase + ra) * DD + col)
                                    = make_float2(v0, v1);
                            }
                            if (rb < real) {
                                *(float2*)(out + (size_t)(rbase + rb) * DD + col)
                                    = make_float2(v2, v3);
                            }
                        } else {
                            // padded rows carry garbage but stay row-local; never stored
                            *(u32*)(sm + A_HI + aoff(ra, col)) = pack2h(v0, v1);
                            *(u32*)(sm + A_HI + aoff(rb, col)) = pack2h(v2, v3);
                        }
                    }
                }
            }
            // next chunk-loop's first __syncthreads orders epilogue writes vs reads
        }
    }
}

extern "C" void kernel_launch(void* const* d_in, const int* in_sizes, int n_in,
                              void* d_out, int out_size) {
    (void)in_sizes; (void)n_in; (void)out_size;
    const float* x    = (const float*)d_in[0];
    const float* w0   = (const float*)d_in[1];
    const float* b0   = (const float*)d_in[2];
    const float* w1   = (const float*)d_in[3];
    const float* b1   = (const float*)d_in[4];
    const float* u1w  = (const float*)d_in[5];
    const float* u1cw = (const float*)d_in[6];
    const float* u1cb = (const float*)d_in[7];
    const float* w2   = (const float*)d_in[8];
    const float* b2   = (const float*)d_in[9];
    const float* u2w  = (const float*)d_in[10];
    const float* u2cw = (const float*)d_in[11];
    const float* u2cb = (const float*)d_in[12];
    const float* wo   = (const float*)d_in[13];
    const float* bo   = (const float*)d_in[14];
    float* out = (float*)d_out;

    cudaFuncSetAttribute(mlp_mma, cudaFuncAttributeMaxDynamicSharedMemorySize, SMEM_TOTAL);

    prep<<<1538, 256>>>(w0, w1, u1cw, w2, u2cw, wo, u1w, u2w);
    mlp_mma<<<NCTA, NTHREADS, SMEM_TOTAL>>>(x, b0, b1, u1cb, b2, u2cb, bo, out);
}